// round 14
// baseline (speedup 1.0000x reference)
#include <cuda_runtime.h>
#include <cuda_fp16.h>
#include <cstdint>

#define D      128      // D_IN = D_OUT
#define NMAX   100000

// Scratch (device globals; no allocation allowed)
__device__ __half g_xh[NMAX * D];   // x rounded to fp16 (GEMM A operand)
__device__ __half g_yh[NMAX * D];   // y = x @ W2, stored fp16

// ============================================================================
// PTX helpers (base ISA: cp.async / ldmatrix / mma.sync / cp.reduce.async.bulk)
// ============================================================================
__device__ __forceinline__ uint32_t smem_to_u32(const void* p) {
    uint32_t a;
    asm("{ .reg .u64 t; cvta.to.shared.u64 t, %1; cvt.u32.u64 %0, t; }"
        : "=r"(a) : "l"(p));
    return a;
}
#define CP_ASYNC16(dst, src, sz) \
    asm volatile("cp.async.cg.shared.global [%0], [%1], 16, %2;" \
        :: "r"(dst), "l"(src), "r"(sz))
#define CP_COMMIT() asm volatile("cp.async.commit_group;" ::: "memory")
#define CP_WAIT1()  asm volatile("cp.async.wait_group 1;"  ::: "memory")

#define LDSM_X4(r0,r1,r2,r3,addr) \
    asm volatile("ldmatrix.sync.aligned.m8n8.x4.shared.b16 {%0,%1,%2,%3}, [%4];" \
        : "=r"(r0), "=r"(r1), "=r"(r2), "=r"(r3) : "r"(addr))
#define LDSM_X4T(r0,r1,r2,r3,addr) \
    asm volatile("ldmatrix.sync.aligned.m8n8.x4.trans.shared.b16 {%0,%1,%2,%3}, [%4];" \
        : "=r"(r0), "=r"(r1), "=r"(r2), "=r"(r3) : "r"(addr))

// fp16 inputs, fp32 accumulate
#define MMA16816F16(c, a, b) \
    asm volatile("mma.sync.aligned.m16n8k16.row.col.f32.f16.f16.f32 " \
        "{%0,%1,%2,%3}, {%4,%5,%6,%7}, {%8,%9}, {%0,%1,%2,%3};" \
        : "+f"((c)[0]), "+f"((c)[1]), "+f"((c)[2]), "+f"((c)[3]) \
        : "r"((a)[0]), "r"((a)[1]), "r"((a)[2]), "r"((a)[3]), \
          "r"((b)[0]), "r"((b)[1]))

// TMA bulk reduce: smem (512B row) -> global row, add.f32, bulk_group completion
#define TMA_REDUCE_ADD_F32(gptr, saddr, bytes) \
    asm volatile("cp.reduce.async.bulk.global.shared::cta.bulk_group.add.f32 " \
        "[%0], [%1], %2;" :: "l"(gptr), "r"(saddr), "r"(bytes) : "memory")
#define BULK_COMMIT() asm volatile("cp.async.bulk.commit_group;" ::: "memory")
#define BULK_WAIT1()  asm volatile("cp.async.bulk.wait_group 1;" ::: "memory")
#define BULK_WAIT0()  asm volatile("cp.async.bulk.wait_group 0;" ::: "memory")
#define FENCE_ASYNC_SHARED() \
    asm volatile("fence.proxy.async.shared::cta;" ::: "memory")

// ============================================================================
// Kernel 1: round x -> fp16 AND zero d_out (gemm_out/scatter RED into it)
// ============================================================================
__global__ void convert_kernel(const float* __restrict__ x,
                               float* __restrict__ out, int n4) {
    int i = blockIdx.x * blockDim.x + threadIdx.x;
    if (i >= n4) return;
    float4 v = reinterpret_cast<const float4*>(x)[i];
    __half2 h0 = __floats2half2_rn(v.x, v.y);
    __half2 h1 = __floats2half2_rn(v.z, v.w);
    reinterpret_cast<uint2*>(g_xh)[i] =
        make_uint2(*(uint32_t*)&h0, *(uint32_t*)&h1);
    reinterpret_cast<float4*>(out)[i] = make_float4(0.f, 0.f, 0.f, 0.f);
}

// ============================================================================
// GEMM core (R13-proven single-term fp16): C = A @ fp16(W[NH]).
//   EPI 0: plain fp16 store to g_yh.   EPI 1: red.add.v2 of (acc+bias) -> out.
//   SMEM: A double-buffered (2 x 32KB) + B fp16 (32KB) = 96KB.
// ============================================================================
#define GT 256
#define AS_OFF(buf)  ((uint32_t)((buf) * 32768))
#define BS_OFFC      ((uint32_t)65536)
#define SM_TOTAL     98304

__device__ __forceinline__ void load_A_tile(uint32_t smem_base, int buf,
                                            int node0, int N, int tid) {
#pragma unroll
    for (int i = 0; i < 8; i++) {
        int idx  = tid + (i << 8);
        int row  = idx >> 4;
        int cc   = idx & 15;
        int node = node0 + row;
        uint32_t sz    = (node < N) ? 16u : 0u;
        uint32_t chunk = (uint32_t)(cc ^ (row & 7));
        uint32_t doff  = (uint32_t)row * 256u + chunk * 16u;
        const __half* sh = g_xh + (size_t)node * D + cc * 8;
        CP_ASYNC16(smem_base + AS_OFF(buf) + doff, sh, sz);
    }
}

template <int NH, int EPI>
__device__ __forceinline__ void gemm_body(const float* __restrict__ W,
                                          const float* __restrict__ bias,
                                          float* __restrict__ outp, int N) {
    extern __shared__ char smem[];
    uint32_t smem_base = smem_to_u32(smem);
    const int tid  = threadIdx.x;
    const int lane = tid & 31;
    const int wid  = tid >> 5;
    const int warp_m = (wid & 3) << 5;
    const int warp_n = (wid >> 2) << 6;
    const int num_tiles = (N + 127) >> 7;

    // B = fp16(W[NH*128 : +128][:])
#pragma unroll
    for (int j = 0; j < 32; j++) {
        int idx = tid + (j << 8);
        int k   = idx >> 6;
        int n   = (idx & 63) << 1;
        const float* wp = W + ((size_t)(NH * 128 + k)) * 128 + n;
        __half2 h = __floats2half2_rn(wp[0], wp[1]);
        uint32_t boff = (uint32_t)k * 256u
                      + (uint32_t)(((n >> 3) ^ (k & 7)) << 4)
                      + (uint32_t)((n & 7) << 1);
        *reinterpret_cast<uint32_t*>(smem + BS_OFFC + boff) = *(uint32_t*)&h;
    }

    int item = blockIdx.x;
    int buf = 0;
    if (item < num_tiles) load_A_tile(smem_base, 0, item << 7, N, tid);
    CP_COMMIT();

    for (; item < num_tiles; item += gridDim.x) {
        const int node0 = item << 7;
        int next = item + gridDim.x;
        if (next < num_tiles) load_A_tile(smem_base, buf ^ 1, next << 7, N, tid);
        CP_COMMIT();
        CP_WAIT1();
        __syncthreads();

        float acc[2][8][4];
#pragma unroll
        for (int mi = 0; mi < 2; mi++)
#pragma unroll
            for (int ni = 0; ni < 8; ni++)
#pragma unroll
                for (int q = 0; q < 4; q++) acc[mi][ni][q] = 0.f;

#pragma unroll
        for (int ks = 0; ks < 8; ks++) {
            uint32_t ah[2][4];
#pragma unroll
            for (int mi = 0; mi < 2; mi++) {
                int row = warp_m + (mi << 4) + (lane & 15);
                int cb  = (ks << 1) + (lane >> 4);
                uint32_t addr = smem_base + AS_OFF(buf)
                              + (uint32_t)row * 256u
                              + (uint32_t)((cb ^ (row & 7)) << 4);
                LDSM_X4(ah[mi][0], ah[mi][1], ah[mi][2], ah[mi][3], addr);
            }
            uint32_t bh[8][2];
#pragma unroll
            for (int nj = 0; nj < 4; nj++) {
                int row = (ks << 4) + (lane & 15);
                int cb  = (warp_n >> 3) + (nj << 1) + (lane >> 4);
                uint32_t addr = smem_base + BS_OFFC
                              + (uint32_t)row * 256u
                              + (uint32_t)((cb ^ (row & 7)) << 4);
                LDSM_X4T(bh[2*nj][0], bh[2*nj][1], bh[2*nj+1][0], bh[2*nj+1][1], addr);
            }
#pragma unroll
            for (int mi = 0; mi < 2; mi++)
#pragma unroll
                for (int ni = 0; ni < 8; ni++)
                    MMA16816F16(acc[mi][ni], ah[mi], bh[ni]);
        }

#pragma unroll
        for (int ni = 0; ni < 8; ni++) {
            int col = warp_n + (ni << 3) + ((lane & 3) << 1);
            float b0 = 0.f, b1 = 0.f;
            if (EPI == 1) { b0 = bias[col]; b1 = bias[col + 1]; }
#pragma unroll
            for (int mi = 0; mi < 2; mi++) {
#pragma unroll
                for (int half = 0; half < 2; half++) {
                    int node = node0 + warp_m + (mi << 4) + (lane >> 2) + half * 8;
                    if (node < N) {
                        float v0 = acc[mi][ni][half * 2 + 0] + b0;
                        float v1 = acc[mi][ni][half * 2 + 1] + b1;
                        if (EPI == 0) {
                            __half2 v = __floats2half2_rn(v0, v1);
                            *reinterpret_cast<__half2*>(
                                g_yh + (size_t)node * D + col) = v;
                        } else {
                            float* p = outp + (size_t)node * D + col;
                            asm volatile(
                                "red.global.add.v2.f32 [%0], {%1, %2};"
                                :: "l"(p), "f"(v0), "f"(v1) : "memory");
                        }
                    }
                }
            }
        }
        __syncthreads();
        buf ^= 1;
    }
}

__global__ __launch_bounds__(GT, 1)
void gemm_y_kernel(const float* __restrict__ W, int N) {
    gemm_body<1, 0>(W, nullptr, nullptr, N);
}
__global__ __launch_bounds__(GT, 1)
void gemm_out_kernel(const float* __restrict__ W,
                     const float* __restrict__ bias,
                     float* __restrict__ out, int N) {
    gemm_body<0, 1>(W, bias, out, N);
}

// ============================================================================
// Kernel: edge scatter via TMA bulk-reduce (R12-proven, unchanged).
// ============================================================================
#define SC_WARPS 8
#define SC_NE    4     // edges per warp

__global__ __launch_bounds__(SC_WARPS * 32)
void scatter_tma_kernel(const int*   __restrict__ esrc,
                        const int*   __restrict__ edst,
                        const float* __restrict__ eval_,
                        float* __restrict__ out,
                        int E) {
    __shared__ float stage[SC_WARPS][2][128];   // 2 x 512B per warp
    const int lane = threadIdx.x & 31;
    const int wid  = threadIdx.x >> 5;
    const int gw   = blockIdx.x * SC_WARPS + wid;
    const int e0   = gw * SC_NE;

    const uint2* y2 = reinterpret_cast<const uint2*>(g_yh);
    uint32_t sa[2];
    sa[0] = smem_to_u32(&stage[wid][0][0]);
    sa[1] = smem_to_u32(&stage[wid][1][0]);

    int issued = 0;
#pragma unroll
    for (int i = 0; i < SC_NE; i++) {
        int e = e0 + i;
        if (e >= E) break;
        int   s = esrc[e];
        int   d = edst[e];
        float v = eval_[e];

        uint2 w = y2[(size_t)s * 32 + lane];
        float2 f0 = __half22float2(*reinterpret_cast<__half2*>(&w.x));
        float2 f1 = __half22float2(*reinterpret_cast<__half2*>(&w.y));
        float4 r  = make_float4(f0.x * v, f0.y * v, f1.x * v, f1.y * v);

        int buf = i & 1;
        if (i >= 2) {
            if (lane == 0) BULK_WAIT1();
            __syncwarp();
        }
        *reinterpret_cast<float4*>(&stage[wid][buf][lane * 4]) = r;
        __syncwarp();

        if (lane == 0) {
            FENCE_ASYNC_SHARED();
            TMA_REDUCE_ADD_F32(out + (size_t)d * D, sa[buf], 512u);
            BULK_COMMIT();
        }
        issued++;
    }
    if (issued > 0 && lane == 0) BULK_WAIT0();
    __syncwarp();
}

// ============================================================================
// Launch: convert(+zero out) -> gemm_y -> fork -> [scatter || gemm_out] -> join
// ============================================================================
extern "C" void kernel_launch(void* const* d_in, const int* in_sizes, int n_in,
                              void* d_out, int out_size) {
    const float* x     = (const float*)d_in[0];
    const int*   esrc  = (const int*)  d_in[1];
    const int*   edst  = (const int*)  d_in[2];
    const float* eval_ = (const float*)d_in[3];
    const float* W     = (const float*)d_in[4];
    const float* bias  = (const float*)d_in[5];
    float*       out   = (float*)d_out;

    const int N = in_sizes[0] / D;     // 100000
    const int E = in_sizes[1];         // 1600000

    static cudaStream_t s1 = nullptr;
    static cudaEvent_t  evFork = nullptr, evJoin = nullptr;
    if (s1 == nullptr) {               // first (uncaptured correctness) call
        cudaStreamCreateWithFlags(&s1, cudaStreamNonBlocking);
        cudaEventCreateWithFlags(&evFork, cudaEventDisableTiming);
        cudaEventCreateWithFlags(&evJoin, cudaEventDisableTiming);
        cudaFuncSetAttribute(gemm_y_kernel,
                             cudaFuncAttributeMaxDynamicSharedMemorySize, SM_TOTAL);
        cudaFuncSetAttribute(gemm_out_kernel,
                             cudaFuncAttributeMaxDynamicSharedMemorySize, SM_TOTAL);
    }

    // 1) round x -> fp16 ; zero out
    {
        int n4 = N * (D / 4);
        convert_kernel<<<(n4 + 255) / 256, 256>>>(x, out, n4);
    }
    // 2) gemm_y: g_yh = fp16(x @ W2)   (main stream; scatter depends on it)
    gemm_y_kernel<<<148, GT, SM_TOTAL>>>(W, N);

    // 3) fork: gemm_out (SM-bound) on side stream, scatter (TMA/LTS-bound)
    //    on main stream — both RED into the zeroed out buffer, so they commute.
    cudaEventRecord(evFork, 0);
    cudaStreamWaitEvent(s1, evFork, 0);
    gemm_out_kernel<<<148, GT, SM_TOTAL, s1>>>(W, bias, out, N);
    {
        int edges_per_block = SC_WARPS * SC_NE;   // 32
        int blocks = (E + edges_per_block - 1) / edges_per_block;
        scatter_tma_kernel<<<blocks, SC_WARPS * 32>>>(esrc, edst, eval_, out, E);
    }
    // join
    cudaEventRecord(evJoin, s1);
    cudaStreamWaitEvent(0, evJoin, 0);
}

// round 15
// speedup vs baseline: 1.0161x; 1.0161x over previous
#include <cuda_runtime.h>
#include <cuda_fp16.h>
#include <cstdint>

#define D      128      // D_IN = D_OUT
#define NMAX   100000

// Scratch (device globals; no allocation allowed)
__device__ __half g_xh[NMAX * D];   // x rounded to fp16 (GEMM A operand)
__device__ __half g_yh[NMAX * D];   // y = x @ W2, stored fp16

// ============================================================================
// PTX helpers (base ISA: cp.async / ldmatrix / mma.sync / cp.reduce.async.bulk)
// ============================================================================
__device__ __forceinline__ uint32_t smem_to_u32(const void* p) {
    uint32_t a;
    asm("{ .reg .u64 t; cvta.to.shared.u64 t, %1; cvt.u32.u64 %0, t; }"
        : "=r"(a) : "l"(p));
    return a;
}
#define CP_ASYNC16(dst, src, sz) \
    asm volatile("cp.async.cg.shared.global [%0], [%1], 16, %2;" \
        :: "r"(dst), "l"(src), "r"(sz))
#define CP_COMMIT() asm volatile("cp.async.commit_group;" ::: "memory")
#define CP_WAIT1()  asm volatile("cp.async.wait_group 1;"  ::: "memory")

#define LDSM_X4(r0,r1,r2,r3,addr) \
    asm volatile("ldmatrix.sync.aligned.m8n8.x4.shared.b16 {%0,%1,%2,%3}, [%4];" \
        : "=r"(r0), "=r"(r1), "=r"(r2), "=r"(r3) : "r"(addr))
#define LDSM_X4T(r0,r1,r2,r3,addr) \
    asm volatile("ldmatrix.sync.aligned.m8n8.x4.trans.shared.b16 {%0,%1,%2,%3}, [%4];" \
        : "=r"(r0), "=r"(r1), "=r"(r2), "=r"(r3) : "r"(addr))

// fp16 inputs, fp32 accumulate
#define MMA16816F16(c, a, b) \
    asm volatile("mma.sync.aligned.m16n8k16.row.col.f32.f16.f16.f32 " \
        "{%0,%1,%2,%3}, {%4,%5,%6,%7}, {%8,%9}, {%0,%1,%2,%3};" \
        : "+f"((c)[0]), "+f"((c)[1]), "+f"((c)[2]), "+f"((c)[3]) \
        : "r"((a)[0]), "r"((a)[1]), "r"((a)[2]), "r"((a)[3]), \
          "r"((b)[0]), "r"((b)[1]))

// TMA bulk reduce: smem (512B row) -> global row, add.f32, bulk_group completion
#define TMA_REDUCE_ADD_F32(gptr, saddr, bytes) \
    asm volatile("cp.reduce.async.bulk.global.shared::cta.bulk_group.add.f32 " \
        "[%0], [%1], %2;" :: "l"(gptr), "r"(saddr), "r"(bytes) : "memory")
#define BULK_COMMIT() asm volatile("cp.async.bulk.commit_group;" ::: "memory")
#define BULK_WAIT1()  asm volatile("cp.async.bulk.wait_group 1;" ::: "memory")
#define BULK_WAIT0()  asm volatile("cp.async.bulk.wait_group 0;" ::: "memory")
#define FENCE_ASYNC_SHARED() \
    asm volatile("fence.proxy.async.shared::cta;" ::: "memory")

// ============================================================================
// Kernel 1: round x -> fp16 (one pass)
// ============================================================================
__global__ void convert_kernel(const float* __restrict__ x, int n4) {
    int i = blockIdx.x * blockDim.x + threadIdx.x;
    if (i >= n4) return;
    float4 v = reinterpret_cast<const float4*>(x)[i];
    __half2 h0 = __floats2half2_rn(v.x, v.y);
    __half2 h1 = __floats2half2_rn(v.z, v.w);
    reinterpret_cast<uint2*>(g_xh)[i] =
        make_uint2(*(uint32_t*)&h0, *(uint32_t*)&h1);
}

// ============================================================================
// Kernel 2: persistent GEMM via mma.sync, single-term fp16 (R13 math),
//   with SMEM-STAGED COALESCED EPILOGUE (new in R15).
//   (m_tile, nh): nh=0 -> d_out = x@W1 + b (fp32) ; nh=1 -> g_yh = x@W2 (fp16)
//   SMEM: A dbl-buf (2x32KB) + B fp16 (32KB) + epi stage (8 x 8704B) = 164KB.
// ============================================================================
#define GT 256
#define AS_OFF(buf)  ((uint32_t)((buf) * 32768))
#define BS_OFFC      ((uint32_t)65536)
#define EP_OFF       ((uint32_t)98304)
#define EP_WARP      8704u              // 32 rows x 272B (padded pitch)
#define SM_TOTAL     (98304 + 8 * 8704) // 167936

__device__ __forceinline__ void load_A_tile(uint32_t smem_base, int buf,
                                            int node0, int N, int tid) {
#pragma unroll
    for (int i = 0; i < 8; i++) {
        int idx  = tid + (i << 8);
        int row  = idx >> 4;
        int cc   = idx & 15;
        int node = node0 + row;
        uint32_t sz    = (node < N) ? 16u : 0u;
        uint32_t chunk = (uint32_t)(cc ^ (row & 7));
        uint32_t doff  = (uint32_t)row * 256u + chunk * 16u;
        const __half* sh = g_xh + (size_t)node * D + cc * 8;
        CP_ASYNC16(smem_base + AS_OFF(buf) + doff, sh, sz);
    }
}

__global__ __launch_bounds__(GT, 1)
void gemm_kernel(const float* __restrict__ W,
                 const float* __restrict__ bias,
                 float* __restrict__ out,
                 int N) {
    extern __shared__ char smem[];
    uint32_t smem_base = smem_to_u32(smem);
    const int tid  = threadIdx.x;
    const int lane = tid & 31;
    const int wid  = tid >> 5;
    const int warp_m = (wid & 3) << 5;
    const int warp_n = (wid >> 2) << 6;

    const int num_tiles = (N + 127) >> 7;
    const int total = num_tiles * 2;
    int cur_nh = -1;

    int item = blockIdx.x;
    int buf = 0;
    if (item < total) load_A_tile(smem_base, 0, (item % num_tiles) << 7, N, tid);
    CP_COMMIT();

    for (; item < total; item += gridDim.x) {
        const int m_tile = item % num_tiles;
        const int nh     = item / num_tiles;
        const int node0  = m_tile << 7;

        int next = item + gridDim.x;
        if (next < total)
            load_A_tile(smem_base, buf ^ 1, (next % num_tiles) << 7, N, tid);
        CP_COMMIT();

        // (re)load B = W[nh*128 : +128][:] rounded to fp16
        if (nh != cur_nh) {
            cur_nh = nh;
#pragma unroll
            for (int j = 0; j < 32; j++) {
                int idx = tid + (j << 8);          // 0..8191 (half2 pairs)
                int k   = idx >> 6;                // 0..127
                int n   = (idx & 63) << 1;         // even col
                float2 w2 = *reinterpret_cast<const float2*>(
                    W + ((size_t)(nh * 128 + k)) * 128 + n);
                __half2 h = __floats2half2_rn(w2.x, w2.y);
                uint32_t boff = (uint32_t)k * 256u
                              + (uint32_t)(((n >> 3) ^ (k & 7)) << 4)
                              + (uint32_t)((n & 7) << 1);
                *reinterpret_cast<uint32_t*>(smem + BS_OFFC + boff) = *(uint32_t*)&h;
            }
        }

        CP_WAIT1();
        __syncthreads();

        float acc[2][8][4];
#pragma unroll
        for (int mi = 0; mi < 2; mi++)
#pragma unroll
            for (int ni = 0; ni < 8; ni++)
#pragma unroll
                for (int q = 0; q < 4; q++) acc[mi][ni][q] = 0.f;

#pragma unroll
        for (int ks = 0; ks < 8; ks++) {
            uint32_t ah[2][4];
#pragma unroll
            for (int mi = 0; mi < 2; mi++) {
                int row = warp_m + (mi << 4) + (lane & 15);
                int cb  = (ks << 1) + (lane >> 4);
                uint32_t addr = smem_base + AS_OFF(buf)
                              + (uint32_t)row * 256u
                              + (uint32_t)((cb ^ (row & 7)) << 4);
                LDSM_X4(ah[mi][0], ah[mi][1], ah[mi][2], ah[mi][3], addr);
            }
            uint32_t bh[8][2];
#pragma unroll
            for (int nj = 0; nj < 4; nj++) {
                int row = (ks << 4) + (lane & 15);
                int cb  = (warp_n >> 3) + (nj << 1) + (lane >> 4);
                uint32_t addr = smem_base + BS_OFFC
                              + (uint32_t)row * 256u
                              + (uint32_t)((cb ^ (row & 7)) << 4);
                LDSM_X4T(bh[2*nj][0], bh[2*nj][1], bh[2*nj+1][0], bh[2*nj+1][1], addr);
            }
#pragma unroll
            for (int mi = 0; mi < 2; mi++)
#pragma unroll
                for (int ni = 0; ni < 8; ni++)
                    MMA16816F16(acc[mi][ni], ah[mi], bh[ni]);
        }

        // ---- epilogue: stage warp tile (32x64 f32) in padded smem, then
        //      coalesced 128B global stores (nh=0) / 8B-per-lane fp16 (nh=1)
        {
            uint32_t ep = smem_base + EP_OFF + (uint32_t)wid * EP_WARP;
#pragma unroll
            for (int ni = 0; ni < 8; ni++) {
                int colw = (ni << 3) + ((lane & 3) << 1);   // warp-local 0..62
                float b0 = 0.f, b1 = 0.f;
                if (nh == 0) {
                    b0 = bias[warp_n + colw];
                    b1 = bias[warp_n + colw + 1];
                }
#pragma unroll
                for (int mi = 0; mi < 2; mi++)
#pragma unroll
                    for (int hf = 0; hf < 2; hf++) {
                        int rl = (mi << 4) + (lane >> 2) + (hf << 3);
                        uint32_t a = ep + (uint32_t)rl * 272u
                                   + (uint32_t)colw * 4u;
                        float v0 = acc[mi][ni][hf * 2 + 0] + b0;
                        float v1 = acc[mi][ni][hf * 2 + 1] + b1;
                        asm volatile("st.shared.v2.f32 [%0], {%1, %2};"
                                     :: "r"(a), "f"(v0), "f"(v1));
                    }
            }
            __syncwarp();
#pragma unroll
            for (int it = 0; it < 16; it++) {
                int rl = (it << 1) + (lane >> 4);          // 0..31
                int cq = lane & 15;
                uint32_t a = ep + (uint32_t)rl * 272u + (uint32_t)cq * 16u;
                float4 v;
                asm volatile("ld.shared.v4.f32 {%0,%1,%2,%3}, [%4];"
                    : "=f"(v.x), "=f"(v.y), "=f"(v.z), "=f"(v.w) : "r"(a));
                int node = node0 + warp_m + rl;
                if (node < N) {
                    int col = warp_n + (cq << 2);
                    if (nh == 0) {
                        *reinterpret_cast<float4*>(
                            out + (size_t)node * D + col) = v;
                    } else {
                        __half2 h0 = __floats2half2_rn(v.x, v.y);
                        __half2 h1 = __floats2half2_rn(v.z, v.w);
                        *reinterpret_cast<uint2*>(g_yh + (size_t)node * D + col)
                            = make_uint2(*(uint32_t*)&h0, *(uint32_t*)&h1);
                    }
                }
            }
            __syncwarp();
        }
        __syncthreads();
        buf ^= 1;
    }
}

// ============================================================================
// Kernel 3: edge scatter via TMA bulk-reduce (R12-proven, unchanged).
// ============================================================================
#define SC_WARPS 8
#define SC_NE    4     // edges per warp

__global__ __launch_bounds__(SC_WARPS * 32)
void scatter_tma_kernel(const int*   __restrict__ esrc,
                        const int*   __restrict__ edst,
                        const float* __restrict__ eval_,
                        float* __restrict__ out,
                        int E) {
    __shared__ float stage[SC_WARPS][2][128];   // 2 x 512B per warp
    const int lane = threadIdx.x & 31;
    const int wid  = threadIdx.x >> 5;
    const int gw   = blockIdx.x * SC_WARPS + wid;
    const int e0   = gw * SC_NE;

    const uint2* y2 = reinterpret_cast<const uint2*>(g_yh);
    uint32_t sa[2];
    sa[0] = smem_to_u32(&stage[wid][0][0]);
    sa[1] = smem_to_u32(&stage[wid][1][0]);

    int issued = 0;
#pragma unroll
    for (int i = 0; i < SC_NE; i++) {
        int e = e0 + i;
        if (e >= E) break;
        int   s = esrc[e];
        int   d = edst[e];
        float v = eval_[e];

        uint2 w = y2[(size_t)s * 32 + lane];
        float2 f0 = __half22float2(*reinterpret_cast<__half2*>(&w.x));
        float2 f1 = __half22float2(*reinterpret_cast<__half2*>(&w.y));
        float4 r  = make_float4(f0.x * v, f0.y * v, f1.x * v, f1.y * v);

        int buf = i & 1;
        if (i >= 2) {
            if (lane == 0) BULK_WAIT1();
            __syncwarp();
        }
        *reinterpret_cast<float4*>(&stage[wid][buf][lane * 4]) = r;
        __syncwarp();

        if (lane == 0) {
            FENCE_ASYNC_SHARED();
            TMA_REDUCE_ADD_F32(out + (size_t)d * D, sa[buf], 512u);
            BULK_COMMIT();
        }
        issued++;
    }
    if (issued > 0 && lane == 0) BULK_WAIT0();
    __syncwarp();
}

// ============================================================================
// Launch (R13 sequential structure)
// ============================================================================
extern "C" void kernel_launch(void* const* d_in, const int* in_sizes, int n_in,
                              void* d_out, int out_size) {
    const float* x     = (const float*)d_in[0];
    const int*   esrc  = (const int*)  d_in[1];
    const int*   edst  = (const int*)  d_in[2];
    const float* eval_ = (const float*)d_in[3];
    const float* W     = (const float*)d_in[4];
    const float* bias  = (const float*)d_in[5];
    float*       out   = (float*)d_out;

    const int N = in_sizes[0] / D;     // 100000
    const int E = in_sizes[1];         // 1600000

    // 1) round x -> fp16
    {
        int n4 = N * (D / 4);
        convert_kernel<<<(n4 + 255) / 256, 256>>>(x, n4);
    }
    // 2) persistent GEMM: d_out = x@W1 + b ; g_yh = fp16(x@W2)
    {
        static bool attr_set = false;
        if (!attr_set) {
            cudaFuncSetAttribute(gemm_kernel,
                                 cudaFuncAttributeMaxDynamicSharedMemorySize,
                                 SM_TOTAL);
            attr_set = true;
        }
        gemm_kernel<<<148, GT, SM_TOTAL>>>(W, bias, out, N);
    }
    // 3) scatter via TMA bulk-reduce
    {
        int edges_per_block = SC_WARPS * SC_NE;   // 32
        int blocks = (E + edges_per_block - 1) / edges_per_block;
        scatter_tma_kernel<<<blocks, SC_WARPS * 32>>>(esrc, edst, eval_, out, E);
    }
}

// round 16
// speedup vs baseline: 1.0347x; 1.0184x over previous
#include <cuda_runtime.h>
#include <cuda_fp16.h>
#include <cstdint>

#define D      128      // D_IN = D_OUT
#define NMAX   100000

// Scratch (device globals; no allocation allowed)
__device__ __half g_xh[NMAX * D];   // x rounded to fp16 (GEMM A operand)
__device__ __half g_yh[NMAX * D];   // y = x @ W2, stored fp16

// ============================================================================
// PTX helpers (base ISA: cp.async / ldmatrix / mma.sync / cp.reduce.async.bulk)
// ============================================================================
__device__ __forceinline__ uint32_t smem_to_u32(const void* p) {
    uint32_t a;
    asm("{ .reg .u64 t; cvta.to.shared.u64 t, %1; cvt.u32.u64 %0, t; }"
        : "=r"(a) : "l"(p));
    return a;
}
#define CP_ASYNC16(dst, src, sz) \
    asm volatile("cp.async.cg.shared.global [%0], [%1], 16, %2;" \
        :: "r"(dst), "l"(src), "r"(sz))
#define CP_COMMIT() asm volatile("cp.async.commit_group;" ::: "memory")
#define CP_WAIT1()  asm volatile("cp.async.wait_group 1;"  ::: "memory")

#define LDSM_X4(r0,r1,r2,r3,addr) \
    asm volatile("ldmatrix.sync.aligned.m8n8.x4.shared.b16 {%0,%1,%2,%3}, [%4];" \
        : "=r"(r0), "=r"(r1), "=r"(r2), "=r"(r3) : "r"(addr))
#define LDSM_X4T(r0,r1,r2,r3,addr) \
    asm volatile("ldmatrix.sync.aligned.m8n8.x4.trans.shared.b16 {%0,%1,%2,%3}, [%4];" \
        : "=r"(r0), "=r"(r1), "=r"(r2), "=r"(r3) : "r"(addr))

// fp16 inputs, fp32 accumulate
#define MMA16816F16(c, a, b) \
    asm volatile("mma.sync.aligned.m16n8k16.row.col.f32.f16.f16.f32 " \
        "{%0,%1,%2,%3}, {%4,%5,%6,%7}, {%8,%9}, {%0,%1,%2,%3};" \
        : "+f"((c)[0]), "+f"((c)[1]), "+f"((c)[2]), "+f"((c)[3]) \
        : "r"((a)[0]), "r"((a)[1]), "r"((a)[2]), "r"((a)[3]), \
          "r"((b)[0]), "r"((b)[1]))

// TMA bulk reduce: smem (512B row) -> global row, add.f32, bulk_group completion
#define TMA_REDUCE_ADD_F32(gptr, saddr, bytes) \
    asm volatile("cp.reduce.async.bulk.global.shared::cta.bulk_group.add.f32 " \
        "[%0], [%1], %2;" :: "l"(gptr), "r"(saddr), "r"(bytes) : "memory")
#define BULK_COMMIT() asm volatile("cp.async.bulk.commit_group;" ::: "memory")
#define BULK_WAIT1()  asm volatile("cp.async.bulk.wait_group 1;" ::: "memory")
#define BULK_WAIT0()  asm volatile("cp.async.bulk.wait_group 0;" ::: "memory")
#define FENCE_ASYNC_SHARED() \
    asm volatile("fence.proxy.async.shared::cta;" ::: "memory")

// ============================================================================
// Kernel 1: round x -> fp16 (one pass)
// ============================================================================
__global__ void convert_kernel(const float* __restrict__ x, int n4) {
    int i = blockIdx.x * blockDim.x + threadIdx.x;
    if (i >= n4) return;
    float4 v = reinterpret_cast<const float4*>(x)[i];
    __half2 h0 = __floats2half2_rn(v.x, v.y);
    __half2 h1 = __floats2half2_rn(v.z, v.w);
    reinterpret_cast<uint2*>(g_xh)[i] =
        make_uint2(*(uint32_t*)&h0, *(uint32_t*)&h1);
}

// ============================================================================
// Kernel 2: persistent GEMM via mma.sync, single-term fp16 (R13 math),
//   NOW 512 threads / 16 warps per CTA (warp tile 32M x 32N) to double the
//   warps per SMSP and hide the LDSM->MMA latency chain.
//   (m_tile, nh): nh=0 -> d_out = x@W1 + b (fp32) ; nh=1 -> g_yh = x@W2 (fp16)
//   SMEM: A double-buffered (2 x 32KB) + B fp16 (32KB) = 96KB.
// ============================================================================
#define GT 512
#define AS_OFF(buf)  ((uint32_t)((buf) * 32768))
#define BS_OFFC      ((uint32_t)65536)
#define SM_TOTAL     98304

__device__ __forceinline__ void load_A_tile(uint32_t smem_base, int buf,
                                            int node0, int N, int tid) {
#pragma unroll
    for (int i = 0; i < 4; i++) {
        int idx  = tid + (i << 9);        // 0..2047 16B chunks (512 threads)
        int row  = idx >> 4;
        int cc   = idx & 15;
        int node = node0 + row;
        uint32_t sz    = (node < N) ? 16u : 0u;
        uint32_t chunk = (uint32_t)(cc ^ (row & 7));
        uint32_t doff  = (uint32_t)row * 256u + chunk * 16u;
        const __half* sh = g_xh + (size_t)node * D + cc * 8;
        CP_ASYNC16(smem_base + AS_OFF(buf) + doff, sh, sz);
    }
}

__global__ __launch_bounds__(GT, 1)
void gemm_kernel(const float* __restrict__ W,
                 const float* __restrict__ bias,
                 float* __restrict__ out,
                 int N) {
    extern __shared__ char smem[];
    uint32_t smem_base = smem_to_u32(smem);
    const int tid  = threadIdx.x;
    const int lane = tid & 31;
    const int wid  = tid >> 5;                 // 0..15
    const int warp_m = (wid & 3) << 5;         // 0,32,64,96
    const int warp_n = (wid >> 2) << 5;        // 0,32,64,96

    const int num_tiles = (N + 127) >> 7;
    const int total = num_tiles * 2;
    int cur_nh = -1;

    int item = blockIdx.x;
    int buf = 0;
    if (item < total) load_A_tile(smem_base, 0, (item % num_tiles) << 7, N, tid);
    CP_COMMIT();

    for (; item < total; item += gridDim.x) {
        const int m_tile = item % num_tiles;
        const int nh     = item / num_tiles;
        const int node0  = m_tile << 7;

        int next = item + gridDim.x;
        if (next < total)
            load_A_tile(smem_base, buf ^ 1, (next % num_tiles) << 7, N, tid);
        CP_COMMIT();

        // (re)load B = W[nh*128 : +128][:] rounded to fp16 (512 threads)
        if (nh != cur_nh) {
            cur_nh = nh;
#pragma unroll
            for (int j = 0; j < 16; j++) {
                int idx = tid + (j << 9);          // 0..8191 (half2 pairs)
                int k   = idx >> 6;                // 0..127
                int n   = (idx & 63) << 1;         // even col
                float2 w2 = *reinterpret_cast<const float2*>(
                    W + ((size_t)(nh * 128 + k)) * 128 + n);
                __half2 h = __floats2half2_rn(w2.x, w2.y);
                uint32_t boff = (uint32_t)k * 256u
                              + (uint32_t)(((n >> 3) ^ (k & 7)) << 4)
                              + (uint32_t)((n & 7) << 1);
                *reinterpret_cast<uint32_t*>(smem + BS_OFFC + boff) = *(uint32_t*)&h;
            }
        }

        CP_WAIT1();
        __syncthreads();

        float acc[2][4][4];
#pragma unroll
        for (int mi = 0; mi < 2; mi++)
#pragma unroll
            for (int ni = 0; ni < 4; ni++)
#pragma unroll
                for (int q = 0; q < 4; q++) acc[mi][ni][q] = 0.f;

#pragma unroll
        for (int ks = 0; ks < 8; ks++) {
            uint32_t ah[2][4];
#pragma unroll
            for (int mi = 0; mi < 2; mi++) {
                int row = warp_m + (mi << 4) + (lane & 15);
                int cb  = (ks << 1) + (lane >> 4);
                uint32_t addr = smem_base + AS_OFF(buf)
                              + (uint32_t)row * 256u
                              + (uint32_t)((cb ^ (row & 7)) << 4);
                LDSM_X4(ah[mi][0], ah[mi][1], ah[mi][2], ah[mi][3], addr);
            }
            uint32_t bh[4][2];
            {
                // two x4-trans LDSMs cover 32 N-columns
#pragma unroll
                for (int nj = 0; nj < 2; nj++) {
                    int row = (ks << 4) + (lane & 15);
                    int cb  = (warp_n >> 3) + (nj << 1) + (lane >> 4);
                    uint32_t addr = smem_base + BS_OFFC
                                  + (uint32_t)row * 256u
                                  + (uint32_t)((cb ^ (row & 7)) << 4);
                    LDSM_X4T(bh[2*nj][0], bh[2*nj][1],
                             bh[2*nj+1][0], bh[2*nj+1][1], addr);
                }
            }
#pragma unroll
            for (int mi = 0; mi < 2; mi++)
#pragma unroll
                for (int ni = 0; ni < 4; ni++)
                    MMA16816F16(acc[mi][ni], ah[mi], bh[ni]);
        }

        // ---- epilogue: direct stores (R13 style) ----
        if (nh == 0) {
#pragma unroll
            for (int ni = 0; ni < 4; ni++) {
                int col = warp_n + (ni << 3) + ((lane & 3) << 1);
                float b0 = bias[col], b1 = bias[col + 1];
#pragma unroll
                for (int mi = 0; mi < 2; mi++) {
                    int r = warp_m + (mi << 4) + (lane >> 2);
                    int node = node0 + r;
                    if (node < N) {
                        float2 v = make_float2(acc[mi][ni][0] + b0, acc[mi][ni][1] + b1);
                        *reinterpret_cast<float2*>(out + (size_t)node * D + col) = v;
                    }
                    int node2 = node + 8;
                    if (node2 < N) {
                        float2 v = make_float2(acc[mi][ni][2] + b0, acc[mi][ni][3] + b1);
                        *reinterpret_cast<float2*>(out + (size_t)node2 * D + col) = v;
                    }
                }
            }
        } else {
#pragma unroll
            for (int ni = 0; ni < 4; ni++) {
                int col = warp_n + (ni << 3) + ((lane & 3) << 1);
#pragma unroll
                for (int mi = 0; mi < 2; mi++) {
                    int r = warp_m + (mi << 4) + (lane >> 2);
                    int node = node0 + r;
                    if (node < N) {
                        __half2 v = __floats2half2_rn(acc[mi][ni][0], acc[mi][ni][1]);
                        *reinterpret_cast<__half2*>(g_yh + (size_t)node * D + col) = v;
                    }
                    int node2 = node + 8;
                    if (node2 < N) {
                        __half2 v = __floats2half2_rn(acc[mi][ni][2], acc[mi][ni][3]);
                        *reinterpret_cast<__half2*>(g_yh + (size_t)node2 * D + col) = v;
                    }
                }
            }
        }
        __syncthreads();
        buf ^= 1;
    }
}

// ============================================================================
// Kernel 3: edge scatter via TMA bulk-reduce (R12-proven, unchanged).
// ============================================================================
#define SC_WARPS 8
#define SC_NE    4     // edges per warp

__global__ __launch_bounds__(SC_WARPS * 32)
void scatter_tma_kernel(const int*   __restrict__ esrc,
                        const int*   __restrict__ edst,
                        const float* __restrict__ eval_,
                        float* __restrict__ out,
                        int E) {
    __shared__ float stage[SC_WARPS][2][128];   // 2 x 512B per warp
    const int lane = threadIdx.x & 31;
    const int wid  = threadIdx.x >> 5;
    const int gw   = blockIdx.x * SC_WARPS + wid;
    const int e0   = gw * SC_NE;

    const uint2* y2 = reinterpret_cast<const uint2*>(g_yh);
    uint32_t sa[2];
    sa[0] = smem_to_u32(&stage[wid][0][0]);
    sa[1] = smem_to_u32(&stage[wid][1][0]);

    int issued = 0;
#pragma unroll
    for (int i = 0; i < SC_NE; i++) {
        int e = e0 + i;
        if (e >= E) break;
        int   s = esrc[e];
        int   d = edst[e];
        float v = eval_[e];

        uint2 w = y2[(size_t)s * 32 + lane];
        float2 f0 = __half22float2(*reinterpret_cast<__half2*>(&w.x));
        float2 f1 = __half22float2(*reinterpret_cast<__half2*>(&w.y));
        float4 r  = make_float4(f0.x * v, f0.y * v, f1.x * v, f1.y * v);

        int buf = i & 1;
        if (i >= 2) {
            if (lane == 0) BULK_WAIT1();
            __syncwarp();
        }
        *reinterpret_cast<float4*>(&stage[wid][buf][lane * 4]) = r;
        __syncwarp();

        if (lane == 0) {
            FENCE_ASYNC_SHARED();
            TMA_REDUCE_ADD_F32(out + (size_t)d * D, sa[buf], 512u);
            BULK_COMMIT();
        }
        issued++;
    }
    if (issued > 0 && lane == 0) BULK_WAIT0();
    __syncwarp();
}

// ============================================================================
// Launch (R13 sequential structure)
// ============================================================================
extern "C" void kernel_launch(void* const* d_in, const int* in_sizes, int n_in,
                              void* d_out, int out_size) {
    const float* x     = (const float*)d_in[0];
    const int*   esrc  = (const int*)  d_in[1];
    const int*   edst  = (const int*)  d_in[2];
    const float* eval_ = (const float*)d_in[3];
    const float* W     = (const float*)d_in[4];
    const float* bias  = (const float*)d_in[5];
    float*       out   = (float*)d_out;

    const int N = in_sizes[0] / D;     // 100000
    const int E = in_sizes[1];         // 1600000

    // 1) round x -> fp16
    {
        int n4 = N * (D / 4);
        convert_kernel<<<(n4 + 255) / 256, 256>>>(x, n4);
    }
    // 2) persistent GEMM: d_out = x@W1 + b ; g_yh = fp16(x@W2)
    {
        static bool attr_set = false;
        if (!attr_set) {
            cudaFuncSetAttribute(gemm_kernel,
                                 cudaFuncAttributeMaxDynamicSharedMemorySize,
                                 SM_TOTAL);
            attr_set = true;
        }
        gemm_kernel<<<148, GT, SM_TOTAL>>>(W, bias, out, N);
    }
    // 3) scatter via TMA bulk-reduce
    {
        int edges_per_block = SC_WARPS * SC_NE;   // 32
        int blocks = (E + edges_per_block - 1) / edges_per_block;
        scatter_tma_kernel<<<blocks, SC_WARPS * 32>>>(esrc, edst, eval_, out, E);
    }
}

// round 17
// speedup vs baseline: 1.0421x; 1.0071x over previous
#include <cuda_runtime.h>
#include <cuda_fp16.h>
#include <cstdint>

#define D      128      // D_IN = D_OUT
#define NMAX   100000

// Scratch (device globals; no allocation allowed)
__device__ __half g_xh[NMAX * D];   // x rounded to fp16 (GEMM A operand)
__device__ __half g_yh[NMAX * D];   // y = x @ W2, stored fp16

// ============================================================================
// PTX helpers (base ISA: cp.async / ldmatrix / mma.sync / cp.reduce.async.bulk)
// ============================================================================
__device__ __forceinline__ uint32_t smem_to_u32(const void* p) {
    uint32_t a;
    asm("{ .reg .u64 t; cvta.to.shared.u64 t, %1; cvt.u32.u64 %0, t; }"
        : "=r"(a) : "l"(p));
    return a;
}
#define CP_ASYNC16(dst, src, sz) \
    asm volatile("cp.async.cg.shared.global [%0], [%1], 16, %2;" \
        :: "r"(dst), "l"(src), "r"(sz))
#define CP_COMMIT() asm volatile("cp.async.commit_group;" ::: "memory")
#define CP_WAIT1()  asm volatile("cp.async.wait_group 1;"  ::: "memory")

#define LDSM_X4(r0,r1,r2,r3,addr) \
    asm volatile("ldmatrix.sync.aligned.m8n8.x4.shared.b16 {%0,%1,%2,%3}, [%4];" \
        : "=r"(r0), "=r"(r1), "=r"(r2), "=r"(r3) : "r"(addr))
#define LDSM_X4T(r0,r1,r2,r3,addr) \
    asm volatile("ldmatrix.sync.aligned.m8n8.x4.trans.shared.b16 {%0,%1,%2,%3}, [%4];" \
        : "=r"(r0), "=r"(r1), "=r"(r2), "=r"(r3) : "r"(addr))

// fp16 inputs, fp32 accumulate
#define MMA16816F16(c, a, b) \
    asm volatile("mma.sync.aligned.m16n8k16.row.col.f32.f16.f16.f32 " \
        "{%0,%1,%2,%3}, {%4,%5,%6,%7}, {%8,%9}, {%0,%1,%2,%3};" \
        : "+f"((c)[0]), "+f"((c)[1]), "+f"((c)[2]), "+f"((c)[3]) \
        : "r"((a)[0]), "r"((a)[1]), "r"((a)[2]), "r"((a)[3]), \
          "r"((b)[0]), "r"((b)[1]))

// TMA bulk reduce: smem (512B row) -> global row, add.f32, bulk_group completion
#define TMA_REDUCE_ADD_F32(gptr, saddr, bytes) \
    asm volatile("cp.reduce.async.bulk.global.shared::cta.bulk_group.add.f32 " \
        "[%0], [%1], %2;" :: "l"(gptr), "r"(saddr), "r"(bytes) : "memory")
#define BULK_COMMIT() asm volatile("cp.async.bulk.commit_group;" ::: "memory")
#define BULK_WAIT1()  asm volatile("cp.async.bulk.wait_group 1;" ::: "memory")
#define BULK_WAIT0()  asm volatile("cp.async.bulk.wait_group 0;" ::: "memory")
#define FENCE_ASYNC_SHARED() \
    asm volatile("fence.proxy.async.shared::cta;" ::: "memory")

// ============================================================================
// Kernel 1: round x -> fp16 (one pass)
// ============================================================================
__global__ void convert_kernel(const float* __restrict__ x, int n4) {
    int i = blockIdx.x * blockDim.x + threadIdx.x;
    if (i >= n4) return;
    float4 v = reinterpret_cast<const float4*>(x)[i];
    __half2 h0 = __floats2half2_rn(v.x, v.y);
    __half2 h1 = __floats2half2_rn(v.z, v.w);
    reinterpret_cast<uint2*>(g_xh)[i] =
        make_uint2(*(uint32_t*)&h0, *(uint32_t*)&h1);
}

// ============================================================================
// Kernel 2: persistent GEMM via mma.sync, single-term fp16 (R13 math),
//   NOW 2 CTAs PER SM (grid=296, __launch_bounds__(256,2)) so one CTA's
//   compute overlaps the other CTA's barrier/cp-wait/epilogue stalls.
//   (m_tile, nh): nh=0 -> d_out = x@W1 + b (fp32) ; nh=1 -> g_yh = x@W2 (fp16)
//   SMEM: A double-buffered (2 x 32KB) + B fp16 (32KB) = 96KB (x2 = 192KB/SM).
// ============================================================================
#define GT 256
#define GGRID 296
#define AS_OFF(buf)  ((uint32_t)((buf) * 32768))
#define BS_OFFC      ((uint32_t)65536)
#define SM_TOTAL     98304

__device__ __forceinline__ void load_A_tile(uint32_t smem_base, int buf,
                                            int node0, int N, int tid) {
#pragma unroll
    for (int i = 0; i < 8; i++) {
        int idx  = tid + (i << 8);
        int row  = idx >> 4;
        int cc   = idx & 15;
        int node = node0 + row;
        uint32_t sz    = (node < N) ? 16u : 0u;
        uint32_t chunk = (uint32_t)(cc ^ (row & 7));
        uint32_t doff  = (uint32_t)row * 256u + chunk * 16u;
        const __half* sh = g_xh + (size_t)node * D + cc * 8;
        CP_ASYNC16(smem_base + AS_OFF(buf) + doff, sh, sz);
    }
}

__global__ __launch_bounds__(GT, 2)
void gemm_kernel(const float* __restrict__ W,
                 const float* __restrict__ bias,
                 float* __restrict__ out,
                 int N) {
    extern __shared__ char smem[];
    uint32_t smem_base = smem_to_u32(smem);
    const int tid  = threadIdx.x;
    const int lane = tid & 31;
    const int wid  = tid >> 5;
    const int warp_m = (wid & 3) << 5;
    const int warp_n = (wid >> 2) << 6;

    const int num_tiles = (N + 127) >> 7;
    const int total = num_tiles * 2;
    int cur_nh = -1;

    int item = blockIdx.x;
    int buf = 0;
    if (item < total) load_A_tile(smem_base, 0, (item % num_tiles) << 7, N, tid);
    CP_COMMIT();

    for (; item < total; item += gridDim.x) {
        const int m_tile = item % num_tiles;
        const int nh     = item / num_tiles;
        const int node0  = m_tile << 7;

        int next = item + gridDim.x;
        if (next < total)
            load_A_tile(smem_base, buf ^ 1, (next % num_tiles) << 7, N, tid);
        CP_COMMIT();

        // (re)load B = W[nh*128 : +128][:] rounded to fp16
        if (nh != cur_nh) {
            cur_nh = nh;
#pragma unroll
            for (int j = 0; j < 32; j++) {
                int idx = tid + (j << 8);          // 0..8191 (half2 pairs)
                int k   = idx >> 6;                // 0..127
                int n   = (idx & 63) << 1;         // even col
                float2 w2 = *reinterpret_cast<const float2*>(
                    W + ((size_t)(nh * 128 + k)) * 128 + n);
                __half2 h = __floats2half2_rn(w2.x, w2.y);
                uint32_t boff = (uint32_t)k * 256u
                              + (uint32_t)(((n >> 3) ^ (k & 7)) << 4)
                              + (uint32_t)((n & 7) << 1);
                *reinterpret_cast<uint32_t*>(smem + BS_OFFC + boff) = *(uint32_t*)&h;
            }
        }

        CP_WAIT1();
        __syncthreads();

        float acc[2][8][4];
#pragma unroll
        for (int mi = 0; mi < 2; mi++)
#pragma unroll
            for (int ni = 0; ni < 8; ni++)
#pragma unroll
                for (int q = 0; q < 4; q++) acc[mi][ni][q] = 0.f;

#pragma unroll
        for (int ks = 0; ks < 8; ks++) {
            uint32_t ah[2][4];
#pragma unroll
            for (int mi = 0; mi < 2; mi++) {
                int row = warp_m + (mi << 4) + (lane & 15);
                int cb  = (ks << 1) + (lane >> 4);
                uint32_t addr = smem_base + AS_OFF(buf)
                              + (uint32_t)row * 256u
                              + (uint32_t)((cb ^ (row & 7)) << 4);
                LDSM_X4(ah[mi][0], ah[mi][1], ah[mi][2], ah[mi][3], addr);
            }
            uint32_t bh[8][2];
#pragma unroll
            for (int nj = 0; nj < 4; nj++) {
                int row = (ks << 4) + (lane & 15);
                int cb  = (warp_n >> 3) + (nj << 1) + (lane >> 4);
                uint32_t addr = smem_base + BS_OFFC
                              + (uint32_t)row * 256u
                              + (uint32_t)((cb ^ (row & 7)) << 4);
                LDSM_X4T(bh[2*nj][0], bh[2*nj][1], bh[2*nj+1][0], bh[2*nj+1][1], addr);
            }
#pragma unroll
            for (int mi = 0; mi < 2; mi++)
#pragma unroll
                for (int ni = 0; ni < 8; ni++)
                    MMA16816F16(acc[mi][ni], ah[mi], bh[ni]);
        }

        if (nh == 0) {
#pragma unroll
            for (int ni = 0; ni < 8; ni++) {
                int col = warp_n + (ni << 3) + ((lane & 3) << 1);
                float b0 = bias[col], b1 = bias[col + 1];
#pragma unroll
                for (int mi = 0; mi < 2; mi++) {
                    int r = warp_m + (mi << 4) + (lane >> 2);
                    int node = node0 + r;
                    if (node < N) {
                        float2 v = make_float2(acc[mi][ni][0] + b0, acc[mi][ni][1] + b1);
                        *reinterpret_cast<float2*>(out + (size_t)node * D + col) = v;
                    }
                    int node2 = node + 8;
                    if (node2 < N) {
                        float2 v = make_float2(acc[mi][ni][2] + b0, acc[mi][ni][3] + b1);
                        *reinterpret_cast<float2*>(out + (size_t)node2 * D + col) = v;
                    }
                }
            }
        } else {
#pragma unroll
            for (int ni = 0; ni < 8; ni++) {
                int col = warp_n + (ni << 3) + ((lane & 3) << 1);
#pragma unroll
                for (int mi = 0; mi < 2; mi++) {
                    int r = warp_m + (mi << 4) + (lane >> 2);
                    int node = node0 + r;
                    if (node < N) {
                        __half2 v = __floats2half2_rn(acc[mi][ni][0], acc[mi][ni][1]);
                        *reinterpret_cast<__half2*>(g_yh + (size_t)node * D + col) = v;
                    }
                    int node2 = node + 8;
                    if (node2 < N) {
                        __half2 v = __floats2half2_rn(acc[mi][ni][2], acc[mi][ni][3]);
                        *reinterpret_cast<__half2*>(g_yh + (size_t)node2 * D + col) = v;
                    }
                }
            }
        }
        __syncthreads();
        buf ^= 1;
    }
}

// ============================================================================
// Kernel 3: edge scatter via TMA bulk-reduce (R12-proven, unchanged).
// ============================================================================
#define SC_WARPS 8
#define SC_NE    4     // edges per warp

__global__ __launch_bounds__(SC_WARPS * 32)
void scatter_tma_kernel(const int*   __restrict__ esrc,
                        const int*   __restrict__ edst,
                        const float* __restrict__ eval_,
                        float* __restrict__ out,
                        int E) {
    __shared__ float stage[SC_WARPS][2][128];   // 2 x 512B per warp
    const int lane = threadIdx.x & 31;
    const int wid  = threadIdx.x >> 5;
    const int gw   = blockIdx.x * SC_WARPS + wid;
    const int e0   = gw * SC_NE;

    const uint2* y2 = reinterpret_cast<const uint2*>(g_yh);
    uint32_t sa[2];
    sa[0] = smem_to_u32(&stage[wid][0][0]);
    sa[1] = smem_to_u32(&stage[wid][1][0]);

    int issued = 0;
#pragma unroll
    for (int i = 0; i < SC_NE; i++) {
        int e = e0 + i;
        if (e >= E) break;
        int   s = esrc[e];
        int   d = edst[e];
        float v = eval_[e];

        uint2 w = y2[(size_t)s * 32 + lane];
        float2 f0 = __half22float2(*reinterpret_cast<__half2*>(&w.x));
        float2 f1 = __half22float2(*reinterpret_cast<__half2*>(&w.y));
        float4 r  = make_float4(f0.x * v, f0.y * v, f1.x * v, f1.y * v);

        int buf = i & 1;
        if (i >= 2) {
            if (lane == 0) BULK_WAIT1();
            __syncwarp();
        }
        *reinterpret_cast<float4*>(&stage[wid][buf][lane * 4]) = r;
        __syncwarp();

        if (lane == 0) {
            FENCE_ASYNC_SHARED();
            TMA_REDUCE_ADD_F32(out + (size_t)d * D, sa[buf], 512u);
            BULK_COMMIT();
        }
        issued++;
    }
    if (issued > 0 && lane == 0) BULK_WAIT0();
    __syncwarp();
}

// ============================================================================
// Launch (R13 sequential structure; GEMM grid doubled for 2 CTAs/SM)
// ============================================================================
extern "C" void kernel_launch(void* const* d_in, const int* in_sizes, int n_in,
                              void* d_out, int out_size) {
    const float* x     = (const float*)d_in[0];
    const int*   esrc  = (const int*)  d_in[1];
    const int*   edst  = (const int*)  d_in[2];
    const float* eval_ = (const float*)d_in[3];
    const float* W     = (const float*)d_in[4];
    const float* bias  = (const float*)d_in[5];
    float*       out   = (float*)d_out;

    const int N = in_sizes[0] / D;     // 100000
    const int E = in_sizes[1];         // 1600000

    // 1) round x -> fp16
    {
        int n4 = N * (D / 4);
        convert_kernel<<<(n4 + 255) / 256, 256>>>(x, n4);
    }
    // 2) persistent GEMM: d_out = x@W1 + b ; g_yh = fp16(x@W2)
    {
        static bool attr_set = false;
        if (!attr_set) {
            cudaFuncSetAttribute(gemm_kernel,
                                 cudaFuncAttributeMaxDynamicSharedMemorySize,
                                 SM_TOTAL);
            attr_set = true;
        }
        gemm_kernel<<<GGRID, GT, SM_TOTAL>>>(W, bias, out, N);
    }
    // 3) scatter via TMA bulk-reduce
    {
        int edges_per_block = SC_WARPS * SC_NE;   // 32
        int blocks = (E + edges_per_block - 1) / edges_per_block;
        scatter_tma_kernel<<<blocks, SC_WARPS * 32>>>(esrc, edst, eval_, out, E);
    }
}